// round 15
// baseline (speedup 1.0000x reference)
#include <cuda_runtime.h>
#include <cuda_bf16.h>
#include <cmath>
#include <cstring>
#include <cstdint>

namespace {
constexpr int D = 192, H = 48, W = 48, PLANE = 2304, VOX = 442368;
constexpr int KK = 3456;
constexpr int KSPLIT = 4, KSEG = 864;

// ---- pack buffer (float offsets) : conv3d weight image ----
constexpr int PK_WT = 663552;
constexpr int WT_U32_HALF = 9504;

// ---- conv3d mma smem (bytes) ----
constexpr int C_XW = 0;
constexpr int C_AH = 24576;
constexpr int C_AL = 79872;
constexpr int C_WH = 135168;
constexpr int C_WL = 173184;
constexpr int C_SMEM = 211200;

// ---- conv2d mma smem: double-buffered kc=48, pitch 112B ----
constexpr int G_AH = 0;
constexpr int G_AL = 7168;
constexpr int G_BH = 14336;
constexpr int G_BL = 35840;
constexpr int GB   = 57344;
constexpr int G_SMEM = 2 * GB;

// ---- mlp: pre-packed weight image ----
constexpr int PW_AH = 0;
constexpr int PW_AL = 5376;
constexpr int PW_BH = 10752;
constexpr int PW_BL = 21504;
constexpr int PW_CH = 32256;
constexpr int PW_CL = 35584;
constexpr int PW_BA = 38912;
constexpr int PW_BB = 39104;
constexpr int PW_BC = 39488;
constexpr int PW_BYTES = 39552;

// ---- mlp smem ----
constexpr int XP = 208;
constexpr int WP = 112;
constexpr int CP = 208;
constexpr int MO_XH = 39552;
constexpr int MO_XL = 92800;
constexpr int MO_EX = 146048;
constexpr int MO_SMEM = 164480;
}

__device__ __align__(16) float g_pack[689680];
__device__ float g_x1[(size_t)24 * VOX];
__device__ __align__(16) __nv_bfloat16 g_imH[(size_t)PLANE * KK];
__device__ __align__(16) __nv_bfloat16 g_imL[(size_t)PLANE * KK];
__device__ __align__(16) __nv_bfloat16 g_w3H[(size_t)D * KK];
__device__ __align__(16) __nv_bfloat16 g_w3L[(size_t)D * KK];
__device__ float g_part[(size_t)KSPLIT * VOX];
__device__ __align__(16) uint32_t g_mlpw[PW_BYTES / 4];

// ---- mma.sync helpers (validated) ----
__device__ __forceinline__ uint32_t smem_u32(const void* p) {
    uint32_t a;
    asm("{ .reg .u64 t; cvta.to.shared.u64 t, %1; cvt.u32.u64 %0, t; }"
        : "=r"(a) : "l"(p));
    return a;
}
#define LDSM4(r, addr) \
    asm volatile("ldmatrix.sync.aligned.m8n8.x4.shared.b16 {%0,%1,%2,%3}, [%4];" \
        : "=r"((r)[0]), "=r"((r)[1]), "=r"((r)[2]), "=r"((r)[3]) : "r"(addr))
#define LDSM2(r, addr) \
    asm volatile("ldmatrix.sync.aligned.m8n8.x2.shared.b16 {%0,%1}, [%2];" \
        : "=r"((r)[0]), "=r"((r)[1]) : "r"(addr))
#define MMA16816(d, a, b) \
    asm volatile("mma.sync.aligned.m16n8k16.row.col.f32.bf16.bf16.f32 " \
        "{%0,%1,%2,%3}, {%4,%5,%6,%7}, {%8,%9}, {%0,%1,%2,%3};" \
        : "+f"((d)[0]), "+f"((d)[1]), "+f"((d)[2]), "+f"((d)[3]) \
        : "r"((a)[0]), "r"((a)[1]), "r"((a)[2]), "r"((a)[3]), \
          "r"((b)[0]), "r"((b)[1]))

__device__ __forceinline__ void split_bf(float v, __nv_bfloat16& h, __nv_bfloat16& l) {
    h = __float2bfloat16(v);
    l = __float2bfloat16(v - __bfloat162float(h));
}
__device__ __forceinline__ uint32_t pack_bf2(__nv_bfloat16 a, __nv_bfloat16 b) {
    __nv_bfloat162 t; t.x = a; t.y = b;
    uint32_t u; memcpy(&u, &t, 4); return u;
}
__device__ __forceinline__ void fsplit2(float v0, float v1,
                                        uint32_t& hi, uint32_t& lo) {
    uint32_t u0 = __float_as_uint(v0), u1 = __float_as_uint(v1);
    asm("prmt.b32 %0, %1, %2, 0x7632;" : "=r"(hi) : "r"(u0), "r"(u1));
    float l0 = v0 - __uint_as_float(u0 & 0xFFFF0000u);
    float l1 = v1 - __uint_as_float(u1 & 0xFFFF0000u);
    asm("cvt.rn.bf16x2.f32 %0, %1, %2;" : "=r"(lo) : "f"(l1), "f"(l0));
}

// =============== K0a: pack conv weights + MLP weight image ===============
__global__ void pack_kernel(const float* __restrict__ W3, const float* __restrict__ W1,
                            const float* __restrict__ Wa, const float* __restrict__ ba,
                            const float* __restrict__ Wb, const float* __restrict__ bb,
                            const float* __restrict__ Wc, const float* __restrict__ bc) {
    int nt = gridDim.x * blockDim.x, tid = blockIdx.x * blockDim.x + threadIdx.x;
    uint32_t* wt = (uint32_t*)(g_pack + PK_WT);
    for (int j = tid; j < 2 * WT_U32_HALF; j += nt) {
        int half = j / WT_U32_HALF, jj = j % WT_U32_HALF;
        int row = jj / 36, col = jj % 36;
        int kw = row / 24, c = row % 24;
        float v[2];
        #pragma unroll
        for (int s = 0; s < 2; s++) {
            int k = col * 2 + s;
            float val = 0.f;
            if (k <= 60) {
                int kd = k / 11, kh = k % 11;
                int flat = kd * 121 + kh * 11 + kw;
                if (flat < 665) val = W1[c * 1331 + flat];
            }
            v[s] = val;
        }
        __nv_bfloat16 h0, l0, h1, l1;
        split_bf(v[0], h0, l0); split_bf(v[1], h1, l1);
        wt[j] = half ? pack_bf2(l0, l1) : pack_bf2(h0, h1);
    }
    for (int i = tid; i < D * KK; i += nt) {
        int kk = i % KK, d = i / KK;
        int ic = kk / 9, t = kk % 9;
        float v = W3[((size_t)d * 384 + ic) * 9 + t];
        __nv_bfloat16 hv, lv; split_bf(v, hv, lv);
        g_w3H[i] = hv; g_w3L[i] = lv;
    }
    for (int i = tid; i < 48 * 16; i += nt) {
        int u = i / 16, k2 = i % 16;
        int c0 = 2 * k2, c1 = c0 + 1;
        float v0 = (c0 < 25) ? Wa[u * 25 + c0] : 0.f;
        float v1 = (c1 < 25) ? Wa[u * 25 + c1] : 0.f;
        __nv_bfloat16 h0, l0, h1, l1;
        split_bf(v0, h0, l0); split_bf(v1, h1, l1);
        g_mlpw[PW_AH / 4 + u * 28 + k2] = pack_bf2(h0, h1);
        g_mlpw[PW_AL / 4 + u * 28 + k2] = pack_bf2(l0, l1);
    }
    for (int i = tid; i < 96 * 24; i += nt) {
        int u = i / 24, k2 = i % 24;
        float v0 = Wb[u * 48 + 2 * k2], v1 = Wb[u * 48 + 2 * k2 + 1];
        __nv_bfloat16 h0, l0, h1, l1;
        split_bf(v0, h0, l0); split_bf(v1, h1, l1);
        g_mlpw[PW_BH / 4 + u * 28 + k2] = pack_bf2(h0, h1);
        g_mlpw[PW_BL / 4 + u * 28 + k2] = pack_bf2(l0, l1);
    }
    for (int i = tid; i < 16 * 48; i += nt) {
        int u = i / 48, k2 = i % 48;
        float v0 = (u < 9) ? Wc[u * 96 + 2 * k2] : 0.f;
        float v1 = (u < 9) ? Wc[u * 96 + 2 * k2 + 1] : 0.f;
        __nv_bfloat16 h0, l0, h1, l1;
        split_bf(v0, h0, l0); split_bf(v1, h1, l1);
        g_mlpw[PW_CH / 4 + u * 52 + k2] = pack_bf2(h0, h1);
        g_mlpw[PW_CL / 4 + u * 52 + k2] = pack_bf2(l0, l1);
    }
    float* fw = (float*)g_mlpw;
    for (int i = tid; i < 48; i += nt) fw[PW_BA / 4 + i] = ba[i];
    for (int i = tid; i < 96; i += nt) fw[PW_BB / 4 + i] = bb[i];
    for (int i = tid; i < 16; i += nt) fw[PW_BC / 4 + i] = (i < 9) ? bc[i] : 0.f;
    for (int i = tid; i < 48 * 12; i += nt) {
        int u = i / 12, k2 = 16 + i % 12;
        g_mlpw[PW_AH / 4 + u * 28 + k2] = 0;
        g_mlpw[PW_AL / 4 + u * 28 + k2] = 0;
    }
    for (int i = tid; i < 96 * 4; i += nt) {
        int u = i / 4, k2 = 24 + i % 4;
        g_mlpw[PW_BH / 4 + u * 28 + k2] = 0;
        g_mlpw[PW_BL / 4 + u * 28 + k2] = 0;
    }
    for (int i = tid; i < 16 * 4; i += nt) {
        int u = i / 4, k2 = 48 + i % 4;
        g_mlpw[PW_CH / 4 + u * 52 + k2] = 0;
        g_mlpw[PW_CL / 4 + u * 52 + k2] = 0;
    }
}

// =============== K0b: im2col v2 (R13-validated) ===============
__global__ __launch_bounds__(256)
void im2col_kernel(const float* __restrict__ hyper) {
    int kk = blockIdx.x * 256 + threadIdx.x;
    if (kk >= KK) return;
    int ic = kk / 9;
    int t = kk - ic * 9;
    int ky = t / 3 - 1, kx = t - (t / 3) * 3 - 1;
    const float* hp = hyper + (size_t)ic * PLANE;
    int px0 = blockIdx.y * 4;
    #pragma unroll
    for (int j = 0; j < 4; j++) {
        int px = px0 + j;
        int h = px / 48, w = px - h * 48;
        int gh = h + ky, gw = w + kx;
        float v = 0.f;
        if (gh >= 0 && gh < 48 && gw >= 0 && gw < 48)
            v = hp[gh * 48 + gw];
        __nv_bfloat16 hv, lv; split_bf(v, hv, lv);
        size_t o = (size_t)px * KK + kk;
        g_imH[o] = hv; g_imL[o] = lv;
    }
}

// =============== K1: conv2d GEMM, cp.async double-buffered (R14-validated) ===============
__global__ __launch_bounds__(256)
void conv2d_mma_kernel() {
    extern __shared__ char s[];
    const uint32_t sb = smem_u32(s);
    const int tid = threadIdx.x;
    const int lane = tid & 31, warp = tid >> 5;
    const int wm = warp >> 2, wn = warp & 3;
    const int gid = lane >> 2, tig = lane & 3;
    const int amat = lane >> 3, arow = lane & 7;
    const int brow = lane & 7, bk = (lane >> 3) & 1, bn8 = (lane >> 4) & 1;

    const int mblk = blockIdx.x % 36, ksp = blockIdx.x / 36;
    const int px0 = mblk * 64;
    const int k0 = ksp * KSEG;

    auto stage = [&](int buf, int koff) {
        char* base = s + buf * GB;
        for (int id = tid; id < 3072; id += 256) {
            int row = id / 12, r2 = id % 12;
            int half = r2 / 6, q = r2 % 6;
            const __nv_bfloat16* src;
            char* dst;
            if (row < 64) {
                src = (half ? g_imL : g_imH) + ((size_t)(px0 + row) * KK + koff);
                dst = base + (half ? G_AL : G_AH) + row * 112;
            } else {
                int dch = row - 64;
                src = (half ? g_w3L : g_w3H) + ((size_t)dch * KK + koff);
                dst = base + (half ? G_BL : G_BH) + dch * 112;
            }
            uint32_t ds = smem_u32(dst + q * 16);
            asm volatile("cp.async.cg.shared.global [%0], [%1], 16;"
                         :: "r"(ds), "l"((const char*)src + q * 16));
        }
        asm volatile("cp.async.commit_group;" ::: "memory");
    };

    float acc[2][6][4];
    #pragma unroll
    for (int mt = 0; mt < 2; mt++)
        #pragma unroll
        for (int n = 0; n < 6; n++)
            #pragma unroll
            for (int c = 0; c < 4; c++) acc[mt][n][c] = 0.f;

    stage(0, k0);
    #pragma unroll 1
    for (int ch = 0; ch < 18; ch++) {
        if (ch + 1 < 18) {
            stage((ch + 1) & 1, k0 + (ch + 1) * 48);
            asm volatile("cp.async.wait_group 1;" ::: "memory");
        } else {
            asm volatile("cp.async.wait_group 0;" ::: "memory");
        }
        __syncthreads();
        const uint32_t bbase = sb + (uint32_t)((ch & 1) * GB);
        #pragma unroll
        for (int j = 0; j < 3; j++) {
            uint32_t Ah[2][4], Al[2][4];
            #pragma unroll
            for (int mt = 0; mt < 2; mt++) {
                uint32_t aoff = (uint32_t)((wm * 32 + mt * 16 + arow + (amat & 1) * 8) * 112
                                           + j * 32 + (amat >> 1) * 16);
                LDSM4(Ah[mt], bbase + G_AH + aoff);
                LDSM4(Al[mt], bbase + G_AL + aoff);
            }
            uint32_t Bh[3][4], Bl[3][4];
            #pragma unroll
            for (int nb = 0; nb < 3; nb++) {
                uint32_t boff = (uint32_t)((wn * 48 + nb * 16 + brow + bn8 * 8) * 112
                                           + j * 32 + bk * 16);
                LDSM4(Bh[nb], bbase + G_BH + boff);
                LDSM4(Bl[nb], bbase + G_BL + boff);
            }
            #pragma unroll
            for (int mt = 0; mt < 2; mt++)
                #pragma unroll
                for (int nb = 0; nb < 3; nb++) {
                    MMA16816(acc[mt][nb * 2],     Ah[mt], Bh[nb]);
                    MMA16816(acc[mt][nb * 2],     Ah[mt], Bl[nb]);
                    MMA16816(acc[mt][nb * 2],     Al[mt], Bh[nb]);
                    MMA16816(acc[mt][nb * 2 + 1], Ah[mt], Bh[nb] + 2);
                    MMA16816(acc[mt][nb * 2 + 1], Ah[mt], Bl[nb] + 2);
                    MMA16816(acc[mt][nb * 2 + 1], Al[mt], Bh[nb] + 2);
                }
        }
        __syncthreads();
    }

    float* op = g_part + (size_t)ksp * VOX;
    #pragma unroll
    for (int mt = 0; mt < 2; mt++) {
        int px = px0 + wm * 32 + mt * 16 + gid;
        #pragma unroll
        for (int n = 0; n < 6; n++) {
            int d0 = wn * 48 + n * 8 + 2 * tig;
            op[(size_t)d0 * PLANE + px]           = acc[mt][n][0];
            op[(size_t)(d0 + 1) * PLANE + px]     = acc[mt][n][1];
            op[(size_t)d0 * PLANE + px + 8]       = acc[mt][n][2];
            op[(size_t)(d0 + 1) * PLANE + px + 8] = acc[mt][n][3];
        }
    }
}

// =============== K2: masked conv3d, kw-split across 12 warps (R11-validated) ===============
__global__ __launch_bounds__(384)
void conv3d_mma_kernel(const float* __restrict__ x, const float* __restrict__ b1) {
    extern __shared__ char cs[];
    const uint32_t sb = smem_u32(cs);
    const int tid = threadIdx.x;
    const int lane = tid & 31, wrp = tid >> 5;
    const int hrow = (wrp < 6) ? wrp : wrp - 6;
    const int khalf = (wrp < 6) ? 0 : 1;
    const int gid = lane >> 2, tig = lane & 3;
    const int amat = lane >> 3, arow = lane & 7;
    const int brow = (lane & 15) & 7, bhf = (lane & 15) >> 3;

    const int d = blockIdx.x >> 3, hb = blockIdx.x & 7;
    const int h0 = hb * 6;

    float* s_xw = (float*)(cs + C_XW);
    for (int i = tid; i < 6 * 16 * 64; i += 384) {
        int s = i >> 10, rem = i & 1023;
        int r = rem >> 6, wxx = rem & 63;
        int sd = d - 5 + s, gh = h0 - 5 + r, gw = wxx - 5;
        float v = 0.f;
        if (sd >= 0 && gh >= 0 && gh < 48 && gw >= 0 && gw < 48)
            v = x[(size_t)sd * PLANE + gh * 48 + gw];
        s_xw[i] = v;
    }
    {
        float4* wdst = (float4*)(cs + C_WH);
        const float4* wsrc = (const float4*)(g_pack + PK_WT);
        for (int i = tid; i < (2 * WT_U32_HALF) / 4; i += 384) wdst[i] = wsrc[i];
    }
    __syncthreads();

    {
        int r = tid;
        int hr = r >> 6, wx = r & 63;
        #pragma unroll
        for (int i = 0; i < 32; i++) {
            const int k0 = 2 * i, k1 = 2 * i + 1;
            float v0 = 0.f, v1 = 0.f;
            if (k0 <= 60) v0 = s_xw[((k0 / 11) * 16 + hr + (k0 % 11)) * 64 + wx];
            if (k1 <= 60) v1 = s_xw[((k1 / 11) * 16 + hr + (k1 % 11)) * 64 + wx];
            uint32_t hv, lv;
            fsplit2(v0, v1, hv, lv);
            *(uint32_t*)(cs + C_AH + r * 144 + i * 4) = hv;
            *(uint32_t*)(cs + C_AL + r * 144 + i * 4) = lv;
        }
    }
    __syncthreads();

    float acc[3][3][4];
    #pragma unroll
    for (int mt = 0; mt < 3; mt++)
        #pragma unroll
        for (int n = 0; n < 3; n++)
            #pragma unroll
            for (int c = 0; c < 4; c++) acc[mt][n][c] = 0.f;

    const int kw_lo = khalf * 6, kw_hi = khalf ? 11 : 6;
    #pragma unroll 1
    for (int kw = kw_lo; kw < kw_hi; kw++) {
        #pragma unroll
        for (int k16 = 0; k16 < 4; k16++) {
            uint32_t bh[3][2], bl[3][2];
            #pragma unroll
            for (int n = 0; n < 3; n++) {
                uint32_t boff = (uint32_t)((kw * 24 + n * 8 + brow) * 144 + k16 * 32 + bhf * 16);
                LDSM2(bh[n], sb + C_WH + boff);
                LDSM2(bl[n], sb + C_WL + boff);
            }
            #pragma unroll
            for (int mt = 0; mt < 3; mt++) {
                int rowbase = hrow * 64 + mt * 16 + kw;
                uint32_t aoff = (uint32_t)((rowbase + arow + (amat & 1) * 8) * 144
                                           + k16 * 32 + (amat >> 1) * 16);
                uint32_t Ah[4], Al[4];
                LDSM4(Ah, sb + C_AH + aoff);
                LDSM4(Al, sb + C_AL + aoff);
                #pragma unroll
                for (int n = 0; n < 3; n++) {
                    MMA16816(acc[mt][n], Ah, bh[n]);
                    MMA16816(acc[mt][n], Ah, bl[n]);
                    MMA16816(acc[mt][n], Al, bh[n]);
                }
            }
        }
    }

    __syncthreads();
    float* exch = (float*)(cs + C_AL);
    if (khalf == 1) {
        float* e = exch + ((wrp - 6) * 32 + lane) * 37;
        #pragma unroll
        for (int mt = 0; mt < 3; mt++)
            #pragma unroll
            for (int n = 0; n < 3; n++)
                #pragma unroll
                for (int c = 0; c < 4; c++)
                    e[(mt * 3 + n) * 4 + c] = acc[mt][n][c];
    }
    __syncthreads();
    if (khalf == 0) {
        const float* e = exch + (wrp * 32 + lane) * 37;
        float bb1[3][2];
        #pragma unroll
        for (int n = 0; n < 3; n++) {
            int c0 = n * 8 + 2 * tig;
            bb1[n][0] = b1[c0]; bb1[n][1] = b1[c0 + 1];
        }
        const int h_glob = h0 + hrow;
        #pragma unroll
        for (int mt = 0; mt < 3; mt++) {
            int px0 = mt * 16 + gid, px1 = px0 + 8;
            #pragma unroll
            for (int n = 0; n < 3; n++) {
                int c0 = n * 8 + 2 * tig;
                const float* ep = e + (mt * 3 + n) * 4;
                float* o0 = g_x1 + ((size_t)d * 24 + c0) * PLANE + h_glob * 48;
                float* o1 = g_x1 + ((size_t)d * 24 + c0 + 1) * PLANE + h_glob * 48;
                o0[px0] = acc[mt][n][0] + ep[0] + bb1[n][0];
                o1[px0] = acc[mt][n][1] + ep[1] + bb1[n][1];
                o0[px1] = acc[mt][n][2] + ep[2] + bb1[n][0];
                o1[px1] = acc[mt][n][3] + ep[3] + bb1[n][1];
            }
        }
    }
}

// =============== K3: MLP, 256 voxels/CTA, fast splits (R14-validated) ===============
__global__ __launch_bounds__(256)
void mlp_mma_kernel(const float* __restrict__ x, const float* __restrict__ b3,
                    float* __restrict__ out)
{
    extern __shared__ char sm_[];
    const uint32_t sb = smem_u32(sm_);
    const int tid = threadIdx.x;
    const int lane = tid & 31, w = tid >> 5;
    const int gid = lane >> 2, tig = lane & 3;

    for (int i = tid; i < PW_BYTES / 16; i += 256)
        ((uint4*)sm_)[i] = ((const uint4*)g_mlpw)[i];

    float* s_ba = (float*)(sm_ + PW_BA);
    float* s_bb = (float*)(sm_ + PW_BB);
    float* s_bc = (float*)(sm_ + PW_BC);
    float* s_ex = (float*)(sm_ + MO_EX);

    const int v = blockIdx.x * 256 + tid;
    const int dd = v / PLANE, p = v % PLANE;
    {
        const float* xb = g_x1 + (size_t)dd * 24 * PLANE + p;
        float t[26];
        #pragma unroll
        for (int c = 0; c < 24; c++) t[c] = xb[(size_t)c * PLANE];
        t[24] = g_part[v] + g_part[VOX + v] + g_part[2 * (size_t)VOX + v]
              + g_part[3 * (size_t)VOX + v] + b3[dd];
        t[25] = 0.f;
        #pragma unroll
        for (int i = 0; i < 13; i++) {
            uint32_t hv, lv;
            fsplit2(t[2 * i], t[2 * i + 1], hv, lv);
            *(uint32_t*)(sm_ + MO_XH + tid * XP + 4 * i) = hv;
            *(uint32_t*)(sm_ + MO_XL + tid * XP + 4 * i) = lv;
        }
        #pragma unroll
        for (int i = 13; i < 16; i++) {
            *(uint32_t*)(sm_ + MO_XH + tid * XP + 4 * i) = 0;
            *(uint32_t*)(sm_ + MO_XL + tid * XP + 4 * i) = 0;
        }
    }
    __syncthreads();

    const int amat = lane >> 3, arow = lane & 7;
    const int bl15 = lane & 15, brow = bl15 & 7, bhf = bl15 >> 3;
    #define AADDR(off, row0, kb, P) \
        (sb + (off) + (uint32_t)(((row0) + arow + (amat & 1) * 8) * (P) + (kb) + (amat >> 1) * 16))
    #define BADDR(off, n0, kb, P) \
        (sb + (off) + (uint32_t)(((n0) + brow) * (P) + (kb) + bhf * 16))

    const int row0 = w * 32;

    float dA[2][6][4];
    #pragma unroll
    for (int m = 0; m < 2; m++)
        #pragma unroll
        for (int n = 0; n < 6; n++)
            #pragma unroll
            for (int c = 0; c < 4; c++) dA[m][n][c] = 0.f;
    {
        uint32_t Ahf[2][2][4], Alf[2][2][4];
        #pragma unroll
        for (int m = 0; m < 2; m++)
            #pragma unroll
            for (int k = 0; k < 2; k++) {
                LDSM4(Ahf[m][k], AADDR(MO_XH, row0 + 16 * m, 32 * k, XP));
                LDSM4(Alf[m][k], AADDR(MO_XL, row0 + 16 * m, 32 * k, XP));
            }
        #pragma unroll
        for (int n = 0; n < 6; n++) {
            uint32_t bh[2][2], bl2[2][2];
            #pragma unroll
            for (int k = 0; k < 2; k++) {
                LDSM2(bh[k],  BADDR(PW_AH, n * 8, 32 * k, WP));
                LDSM2(bl2[k], BADDR(PW_AL, n * 8, 32 * k, WP));
            }
            #pragma unroll
            for (int m = 0; m < 2; m++)
                #pragma unroll
                for (int k = 0; k < 2; k++) {
                    MMA16816(dA[m][n], Ahf[m][k], bh[k]);
                    MMA16816(dA[m][n], Ahf[m][k], bl2[k]);
                    MMA16816(dA[m][n], Alf[m][k], bh[k]);
                }
        }
    }
    #pragma unroll
    for (int m = 0; m < 2; m++)
        #pragma unroll
        for (int n = 0; n < 6; n++) {
            float2 bias = *(float2*)(s_ba + n * 8 + 2 * tig);
            float v0 = fmaxf(dA[m][n][0] + bias.x, 0.f);
            float v1 = fmaxf(dA[m][n][1] + bias.y, 0.f);
            float v2 = fmaxf(dA[m][n][2] + bias.x, 0.f);
            float v3 = fmaxf(dA[m][n][3] + bias.y, 0.f);
            int r1 = row0 + 16 * m + gid, r2 = r1 + 8;
            int cb = (n * 8 + 2 * tig) * 2;
            uint32_t hv, lv;
            fsplit2(v0, v1, hv, lv);
            *(uint32_t*)(sm_ + MO_XH + r1 * XP + cb) = hv;
            *(uint32_t*)(sm_ + MO_XL + r1 * XP + cb) = lv;
            fsplit2(v2, v3, hv, lv);
            *(uint32_t*)(sm_ + MO_XH + r2 * XP + cb) = hv;
            *(uint32_t*)(sm_ + MO_XL + r2 * XP + cb) = lv;
        }
    __syncwarp();

    float dB[2][12][4];
    #pragma unroll
    for (int m = 0; m < 2; m++)
        #pragma unroll
        for (int n = 0; n < 12; n++)
            #pragma unroll
            for (int c = 0; c < 4; c++) dB[m][n][c] = 0.f;
    {
        uint32_t Ahf[2][3][4], Alf[2][3][4];
        #pragma unroll
        for (int m = 0; m < 2; m++)
            #pragma unroll
            for (int k = 0; k < 3; k++) {
                LDSM4(Ahf[m][k], AADDR(MO_XH, row0 + 16 * m, 32 * k, XP));
                LDSM4(Alf[m][k], AADDR(MO_XL, row0 + 16 * m, 32 * k, XP));
            }
        #pragma unroll
        for (int n = 0; n < 12; n++) {
            uint32_t bh[3][2], bl2[3][2];
            #pragma unroll
            for (int k = 0; k < 3; k++) {
                LDSM2(bh[k],  BADDR(PW_BH, n * 8, 32 * k, WP));
                LDSM2(bl2[k], BADDR(PW_BL, n * 8, 32 * k, WP));
            }
            #pragma unroll
            for (int m = 0; m < 2; m++)
                #pragma unroll
                for (int k = 0; k < 3; k++) {
                    MMA16816(dB[m][n], Ahf[m][k], bh[k]);
                    MMA16816(dB[m][n], Ahf[m][k], bl2[k]);
                    MMA16816(dB[m][n], Alf[m][k], bh[k]);
                }
        }
    }
    #pragma unroll
    for (int m = 0; m < 2; m++)
        #pragma unroll
        for (int n = 0; n < 12; n++) {
            float2 bias = *(float2*)(s_bb + n * 8 + 2 * tig);
            float v0 = fmaxf(dB[m][n][0] + bias.x, 0.f);
            float v1 = fmaxf(dB[m][n][1] + bias.y, 0.f);
            float v2 = fmaxf(dB[m][n][2] + bias.x, 0.f);
            float v3 = fmaxf(dB[m][n][3] + bias.y, 0.f);
            int r1 = row0 + 16 * m + gid, r2 = r1 + 8;
            int cb = (n * 8 + 2 * tig) * 2;
            uint32_t hv, lv;
            fsplit2(v0, v1, hv, lv);
            *(uint32_t*)(sm_ + MO_XH + r1 * XP + cb) = hv;
            *(uint32_t*)(sm_ + MO_XL + r1 * XP + cb) = lv;
            fsplit2(v2, v3, hv, lv);
            *(uint32_t*)(sm_ + MO_XH + r2 * XP + cb) = hv;
            *(uint32_t*)(sm_ + MO_XL + r2 * XP + cb) = lv;
        }
    __syncwarp();

    float dC[2][2][4];
    #pragma unroll
    for (int m = 0; m < 2; m++)
        #pragma unroll
        for (int n = 0; n < 2; n++)
            #pragma unroll
            for (int c = 0; c < 4; c++) dC[m][n][c] = 0.f;
    {
        uint32_t Ahf[2][6][4], Alf[2][6][4];
        #pragma unroll
        for (int m = 0; m < 2; m++)
            #pragma unroll
            for (int k = 0; k < 6; k++) {
                LDSM4(Ahf[m][k], AADDR(MO_XH, row0 + 16 * m, 32 * k, XP));
                LDSM4(Alf[m][k], AADDR(MO_XL, row0 + 16 * m, 32 * k, XP));
            }
        #pragma unroll
        for (int n = 0; n < 2; n++) {
            #pragma unroll
            for (int k = 0; k < 6; k++) {
                uint32_t bh[2], bl2[2];
                LDSM2(bh,  BADDR(PW_CH, n * 8, 32 * k, CP));
                LDSM2(bl2, BADDR(PW_CL, n * 8, 32 * k, CP));
                #pragma unroll
                for (int m = 0; m < 2; m++) {
                    MMA16816(dC[m][n], Ahf[m][k], bh);
                    MMA16816(dC[m][n], Ahf[m][k], bl2);
                    MMA16816(dC[m][n], Alf[m][k], bh);
                }
            }
        }
    }

    #pragma unroll
    for (int m = 0; m < 2; m++)
        #pragma unroll
        for (int n = 0; n < 2; n++) {
            int r1 = row0 + 16 * m + gid, r2 = r1 + 8;
            int cc = n * 8 + 2 * tig;
            s_ex[r1 * 18 + cc]     = dC[m][n][0];
            s_ex[r1 * 18 + cc + 1] = dC[m][n][1];
            s_ex[r2 * 18 + cc]     = dC[m][n][2];
            s_ex[r2 * 18 + cc + 1] = dC[m][n][3];
        }
    __syncwarp();

    float o9[9];
    #pragma unroll
    for (int o = 0; o < 9; o++) o9[o] = s_ex[tid * 18 + o] + s_bc[o];

    float xv = x[v];
    float mx = fmaxf(o9[6], fmaxf(o9[7], o9[8]));
    float e0 = expf(o9[6] - mx), e1 = expf(o9[7] - mx), e2 = expf(o9[8] - mx);
    float inv = 1.f / (e0 + e1 + e2);
    float wsm[3] = {e0 * inv, e1 * inv, e2 * inv};

    float p3 = 0.f;
    #pragma unroll
    for (int k = 0; k < 3; k++) {
        float mu = o9[k];
        float scv = o9[3 + k];
        if (scv == 0.f) scv = 1e-9f;
        scv = fabsf(scv);
        float invs = 1.f / scv;
        float l = fabsf(normcdff((xv + 0.5f - mu) * invs)
                      - normcdff((xv - 0.5f - mu) * invs));
        p3 = fmaf(wsm[k], l, p3);
    }

    out[v] = p3;
    #pragma unroll
    for (int o = 0; o < 9; o++)
        out[(size_t)VOX + (size_t)o * VOX + v] = o9[o];
    #undef AADDR
    #undef BADDR
}

extern "C" void kernel_launch(void* const* d_in, const int* in_sizes, int n_in,
                              void* d_out, int out_size) {
    const float* x     = (const float*)d_in[0];
    const float* hyper = (const float*)d_in[1];
    const float* W3    = (const float*)d_in[2];
    const float* b3    = (const float*)d_in[3];
    const float* W1    = (const float*)d_in[4];
    const float* b1    = (const float*)d_in[5];
    const float* Wa    = (const float*)d_in[6];
    const float* ba    = (const float*)d_in[7];
    const float* Wb    = (const float*)d_in[8];
    const float* bb    = (const float*)d_in[9];
    const float* Wc    = (const float*)d_in[10];
    const float* bc    = (const float*)d_in[11];
    float* out = (float*)d_out;

    // One-time creation of a side stream + fork/join events (host objects,
    // not device allocations; created on the first, uncaptured call).
    static cudaStream_t s2 = nullptr;
    static cudaEvent_t eFork = nullptr, eJoin = nullptr;
    if (s2 == nullptr) {
        cudaStreamCreateWithFlags(&s2, cudaStreamNonBlocking);
        cudaEventCreateWithFlags(&eFork, cudaEventDisableTiming);
        cudaEventCreateWithFlags(&eJoin, cudaEventDisableTiming);
        cudaFuncSetAttribute(conv3d_mma_kernel,
                             cudaFuncAttributeMaxDynamicSharedMemorySize, C_SMEM);
        cudaFuncSetAttribute(conv2d_mma_kernel,
                             cudaFuncAttributeMaxDynamicSharedMemorySize, G_SMEM);
        cudaFuncSetAttribute(mlp_mma_kernel,
                             cudaFuncAttributeMaxDynamicSharedMemorySize, MO_SMEM);
    }

    // main stream: pack -> fork -> (im2col, conv2d)  ||  s2: conv3d
    pack_kernel<<<256, 256>>>(W3, W1, Wa, ba, Wb, bb, Wc, bc);
    cudaEventRecord(eFork, 0);
    cudaStreamWaitEvent(s2, eFork, 0);

    conv3d_mma_kernel<<<192 * 8, 384, C_SMEM, s2>>>(x, b1);

    im2col_kernel<<<dim3((KK + 255) / 256, PLANE / 4), 256>>>(hyper);
    conv2d_mma_kernel<<<36 * KSPLIT, 256, G_SMEM>>>();

    cudaEventRecord(eJoin, s2);
    cudaStreamWaitEvent(0, eJoin, 0);

    mlp_mma_kernel<<<VOX / 256, 256, MO_SMEM>>>(x, b3, out);
}

// round 16
// speedup vs baseline: 1.0664x; 1.0664x over previous
#include <cuda_runtime.h>
#include <cuda_bf16.h>
#include <cmath>
#include <cstring>
#include <cstdint>

namespace {
constexpr int D = 192, H = 48, W = 48, PLANE = 2304, VOX = 442368;
constexpr int KK = 3456;
constexpr int KSPLIT = 4, KSEG = 864;

// ---- pack buffer (float offsets) : conv3d weight image ----
constexpr int PK_WT = 663552;
constexpr int WT_U32_HALF = 9504;

// ---- conv3d mma smem (bytes) ----
constexpr int C_XW = 0;
constexpr int C_AH = 24576;
constexpr int C_AL = 79872;
constexpr int C_WH = 135168;
constexpr int C_WL = 173184;
constexpr int C_SMEM = 211200;

// ---- conv2d mma smem: double-buffered kc=48, pitch 112B ----
constexpr int G_AH = 0;
constexpr int G_AL = 7168;
constexpr int G_BH = 14336;
constexpr int G_BL = 35840;
constexpr int GB   = 57344;
constexpr int G_SMEM = 2 * GB;

// ---- mlp: pre-packed weight image ----
constexpr int PW_AH = 0;
constexpr int PW_AL = 5376;
constexpr int PW_BH = 10752;
constexpr int PW_BL = 21504;
constexpr int PW_CH = 32256;
constexpr int PW_CL = 35584;
constexpr int PW_BA = 38912;
constexpr int PW_BB = 39104;
constexpr int PW_BC = 39488;
constexpr int PW_BYTES = 39552;

// ---- mlp smem ----
constexpr int XP = 208;
constexpr int WP = 112;
constexpr int CP = 208;
constexpr int MO_XH = 39552;
constexpr int MO_XL = 92800;
constexpr int MO_EX = 146048;
constexpr int MO_SMEM = 164480;
}

__device__ __align__(16) float g_pack[689680];
__device__ float g_x1[(size_t)24 * VOX];
__device__ __align__(16) __nv_bfloat16 g_imH[(size_t)PLANE * KK];
__device__ __align__(16) __nv_bfloat16 g_imL[(size_t)PLANE * KK];
__device__ __align__(16) __nv_bfloat16 g_w3H[(size_t)D * KK];
__device__ __align__(16) __nv_bfloat16 g_w3L[(size_t)D * KK];
__device__ float g_part[(size_t)KSPLIT * VOX];
__device__ __align__(16) uint32_t g_mlpw[PW_BYTES / 4];

// ---- mma.sync helpers (validated) ----
__device__ __forceinline__ uint32_t smem_u32(const void* p) {
    uint32_t a;
    asm("{ .reg .u64 t; cvta.to.shared.u64 t, %1; cvt.u32.u64 %0, t; }"
        : "=r"(a) : "l"(p));
    return a;
}
#define LDSM4(r, addr) \
    asm volatile("ldmatrix.sync.aligned.m8n8.x4.shared.b16 {%0,%1,%2,%3}, [%4];" \
        : "=r"((r)[0]), "=r"((r)[1]), "=r"((r)[2]), "=r"((r)[3]) : "r"(addr))
#define LDSM2(r, addr) \
    asm volatile("ldmatrix.sync.aligned.m8n8.x2.shared.b16 {%0,%1}, [%2];" \
        : "=r"((r)[0]), "=r"((r)[1]) : "r"(addr))
#define MMA16816(d, a, b) \
    asm volatile("mma.sync.aligned.m16n8k16.row.col.f32.bf16.bf16.f32 " \
        "{%0,%1,%2,%3}, {%4,%5,%6,%7}, {%8,%9}, {%0,%1,%2,%3};" \
        : "+f"((d)[0]), "+f"((d)[1]), "+f"((d)[2]), "+f"((d)[3]) \
        : "r"((a)[0]), "r"((a)[1]), "r"((a)[2]), "r"((a)[3]), \
          "r"((b)[0]), "r"((b)[1]))

__device__ __forceinline__ void split_bf(float v, __nv_bfloat16& h, __nv_bfloat16& l) {
    h = __float2bfloat16(v);
    l = __float2bfloat16(v - __bfloat162float(h));
}
__device__ __forceinline__ uint32_t pack_bf2(__nv_bfloat16 a, __nv_bfloat16 b) {
    __nv_bfloat162 t; t.x = a; t.y = b;
    uint32_t u; memcpy(&u, &t, 4); return u;
}
__device__ __forceinline__ void fsplit2(float v0, float v1,
                                        uint32_t& hi, uint32_t& lo) {
    uint32_t u0 = __float_as_uint(v0), u1 = __float_as_uint(v1);
    asm("prmt.b32 %0, %1, %2, 0x7632;" : "=r"(hi) : "r"(u0), "r"(u1));
    float l0 = v0 - __uint_as_float(u0 & 0xFFFF0000u);
    float l1 = v1 - __uint_as_float(u1 & 0xFFFF0000u);
    asm("cvt.rn.bf16x2.f32 %0, %1, %2;" : "=r"(lo) : "f"(l1), "f"(l0));
}

// =============== K0a: pack conv weights + MLP weight image ===============
__global__ void pack_kernel(const float* __restrict__ W3, const float* __restrict__ W1,
                            const float* __restrict__ Wa, const float* __restrict__ ba,
                            const float* __restrict__ Wb, const float* __restrict__ bb,
                            const float* __restrict__ Wc, const float* __restrict__ bc) {
    int nt = gridDim.x * blockDim.x, tid = blockIdx.x * blockDim.x + threadIdx.x;
    uint32_t* wt = (uint32_t*)(g_pack + PK_WT);
    for (int j = tid; j < 2 * WT_U32_HALF; j += nt) {
        int half = j / WT_U32_HALF, jj = j % WT_U32_HALF;
        int row = jj / 36, col = jj % 36;
        int kw = row / 24, c = row % 24;
        float v[2];
        #pragma unroll
        for (int s = 0; s < 2; s++) {
            int k = col * 2 + s;
            float val = 0.f;
            if (k <= 60) {
                int kd = k / 11, kh = k % 11;
                int flat = kd * 121 + kh * 11 + kw;
                if (flat < 665) val = W1[c * 1331 + flat];
            }
            v[s] = val;
        }
        __nv_bfloat16 h0, l0, h1, l1;
        split_bf(v[0], h0, l0); split_bf(v[1], h1, l1);
        wt[j] = half ? pack_bf2(l0, l1) : pack_bf2(h0, h1);
    }
    for (int i = tid; i < D * KK; i += nt) {
        int kk = i % KK, d = i / KK;
        int ic = kk / 9, t = kk % 9;
        float v = W3[((size_t)d * 384 + ic) * 9 + t];
        __nv_bfloat16 hv, lv; split_bf(v, hv, lv);
        g_w3H[i] = hv; g_w3L[i] = lv;
    }
    for (int i = tid; i < 48 * 16; i += nt) {
        int u = i / 16, k2 = i % 16;
        int c0 = 2 * k2, c1 = c0 + 1;
        float v0 = (c0 < 25) ? Wa[u * 25 + c0] : 0.f;
        float v1 = (c1 < 25) ? Wa[u * 25 + c1] : 0.f;
        __nv_bfloat16 h0, l0, h1, l1;
        split_bf(v0, h0, l0); split_bf(v1, h1, l1);
        g_mlpw[PW_AH / 4 + u * 28 + k2] = pack_bf2(h0, h1);
        g_mlpw[PW_AL / 4 + u * 28 + k2] = pack_bf2(l0, l1);
    }
    for (int i = tid; i < 96 * 24; i += nt) {
        int u = i / 24, k2 = i % 24;
        float v0 = Wb[u * 48 + 2 * k2], v1 = Wb[u * 48 + 2 * k2 + 1];
        __nv_bfloat16 h0, l0, h1, l1;
        split_bf(v0, h0, l0); split_bf(v1, h1, l1);
        g_mlpw[PW_BH / 4 + u * 28 + k2] = pack_bf2(h0, h1);
        g_mlpw[PW_BL / 4 + u * 28 + k2] = pack_bf2(l0, l1);
    }
    for (int i = tid; i < 16 * 48; i += nt) {
        int u = i / 48, k2 = i % 48;
        float v0 = (u < 9) ? Wc[u * 96 + 2 * k2] : 0.f;
        float v1 = (u < 9) ? Wc[u * 96 + 2 * k2 + 1] : 0.f;
        __nv_bfloat16 h0, l0, h1, l1;
        split_bf(v0, h0, l0); split_bf(v1, h1, l1);
        g_mlpw[PW_CH / 4 + u * 52 + k2] = pack_bf2(h0, h1);
        g_mlpw[PW_CL / 4 + u * 52 + k2] = pack_bf2(l0, l1);
    }
    float* fw = (float*)g_mlpw;
    for (int i = tid; i < 48; i += nt) fw[PW_BA / 4 + i] = ba[i];
    for (int i = tid; i < 96; i += nt) fw[PW_BB / 4 + i] = bb[i];
    for (int i = tid; i < 16; i += nt) fw[PW_BC / 4 + i] = (i < 9) ? bc[i] : 0.f;
    for (int i = tid; i < 48 * 12; i += nt) {
        int u = i / 12, k2 = 16 + i % 12;
        g_mlpw[PW_AH / 4 + u * 28 + k2] = 0;
        g_mlpw[PW_AL / 4 + u * 28 + k2] = 0;
    }
    for (int i = tid; i < 96 * 4; i += nt) {
        int u = i / 4, k2 = 24 + i % 4;
        g_mlpw[PW_BH / 4 + u * 28 + k2] = 0;
        g_mlpw[PW_BL / 4 + u * 28 + k2] = 0;
    }
    for (int i = tid; i < 16 * 4; i += nt) {
        int u = i / 4, k2 = 48 + i % 4;
        g_mlpw[PW_CH / 4 + u * 52 + k2] = 0;
        g_mlpw[PW_CL / 4 + u * 52 + k2] = 0;
    }
}

// =============== K0b: im2col v2 (R13-validated) ===============
__global__ __launch_bounds__(256)
void im2col_kernel(const float* __restrict__ hyper) {
    int kk = blockIdx.x * 256 + threadIdx.x;
    if (kk >= KK) return;
    int ic = kk / 9;
    int t = kk - ic * 9;
    int ky = t / 3 - 1, kx = t - (t / 3) * 3 - 1;
    const float* hp = hyper + (size_t)ic * PLANE;
    int px0 = blockIdx.y * 4;
    #pragma unroll
    for (int j = 0; j < 4; j++) {
        int px = px0 + j;
        int h = px / 48, w = px - h * 48;
        int gh = h + ky, gw = w + kx;
        float v = 0.f;
        if (gh >= 0 && gh < 48 && gw >= 0 && gw < 48)
            v = hp[gh * 48 + gw];
        __nv_bfloat16 hv, lv; split_bf(v, hv, lv);
        size_t o = (size_t)px * KK + kk;
        g_imH[o] = hv; g_imL[o] = lv;
    }
}

// =============== K1: conv2d GEMM, cp.async double-buffered, hoisted staging ===============
__global__ __launch_bounds__(256)
void conv2d_mma_kernel() {
    extern __shared__ char s[];
    const uint32_t sb = smem_u32(s);
    const int tid = threadIdx.x;
    const int lane = tid & 31, warp = tid >> 5;
    const int wm = warp >> 2, wn = warp & 3;
    const int gid = lane >> 2, tig = lane & 3;
    const int amat = lane >> 3, arow = lane & 7;
    const int brow = lane & 7, bk = (lane >> 3) & 1, bn8 = (lane >> 4) & 1;

    const int mblk = blockIdx.x % 36, ksp = blockIdx.x / 36;
    const int px0 = mblk * 64;
    const int k0 = ksp * KSEG;

    // Precompute the 12 staging slots once (chunk-invariant); per chunk we only
    // add koff*2 bytes to src and buf*GB to dst.
    const char* ssrc[12];
    uint32_t sdst[12];
    #pragma unroll
    for (int sl = 0; sl < 12; sl++) {
        int id = tid + sl * 256;
        int row = id / 12, r2 = id % 12;
        int half = r2 / 6, q = r2 % 6;
        if (row < 64) {
            ssrc[sl] = (const char*)((half ? g_imL : g_imH)
                       + ((size_t)(px0 + row) * KK + k0)) + q * 16;
            sdst[sl] = sb + (uint32_t)((half ? G_AL : G_AH) + row * 112 + q * 16);
        } else {
            int dch = row - 64;
            ssrc[sl] = (const char*)((half ? g_w3L : g_w3H)
                       + ((size_t)dch * KK + k0)) + q * 16;
            sdst[sl] = sb + (uint32_t)((half ? G_BL : G_BH) + dch * 112 + q * 16);
        }
    }

    auto stage = [&](int buf, int chunk) {
        const uint32_t boff = (uint32_t)(buf * GB);
        const int soff = chunk * 96;   // 48 bf16 * 2 bytes
        #pragma unroll
        for (int sl = 0; sl < 12; sl++) {
            asm volatile("cp.async.cg.shared.global [%0], [%1], 16;"
                         :: "r"(sdst[sl] + boff), "l"(ssrc[sl] + soff));
        }
        asm volatile("cp.async.commit_group;" ::: "memory");
    };

    float acc[2][6][4];
    #pragma unroll
    for (int mt = 0; mt < 2; mt++)
        #pragma unroll
        for (int n = 0; n < 6; n++)
            #pragma unroll
            for (int c = 0; c < 4; c++) acc[mt][n][c] = 0.f;

    stage(0, 0);
    #pragma unroll 1
    for (int ch = 0; ch < 18; ch++) {
        if (ch + 1 < 18) {
            stage((ch + 1) & 1, ch + 1);
            asm volatile("cp.async.wait_group 1;" ::: "memory");
        } else {
            asm volatile("cp.async.wait_group 0;" ::: "memory");
        }
        __syncthreads();
        const uint32_t bbase = sb + (uint32_t)((ch & 1) * GB);
        #pragma unroll
        for (int j = 0; j < 3; j++) {
            uint32_t Ah[2][4], Al[2][4];
            #pragma unroll
            for (int mt = 0; mt < 2; mt++) {
                uint32_t aoff = (uint32_t)((wm * 32 + mt * 16 + arow + (amat & 1) * 8) * 112
                                           + j * 32 + (amat >> 1) * 16);
                LDSM4(Ah[mt], bbase + G_AH + aoff);
                LDSM4(Al[mt], bbase + G_AL + aoff);
            }
            uint32_t Bh[3][4], Bl[3][4];
            #pragma unroll
            for (int nb = 0; nb < 3; nb++) {
                uint32_t boff = (uint32_t)((wn * 48 + nb * 16 + brow + bn8 * 8) * 112
                                           + j * 32 + bk * 16);
                LDSM4(Bh[nb], bbase + G_BH + boff);
                LDSM4(Bl[nb], bbase + G_BL + boff);
            }
            #pragma unroll
            for (int mt = 0; mt < 2; mt++)
                #pragma unroll
                for (int nb = 0; nb < 3; nb++) {
                    MMA16816(acc[mt][nb * 2],     Ah[mt], Bh[nb]);
                    MMA16816(acc[mt][nb * 2],     Ah[mt], Bl[nb]);
                    MMA16816(acc[mt][nb * 2],     Al[mt], Bh[nb]);
                    MMA16816(acc[mt][nb * 2 + 1], Ah[mt], Bh[nb] + 2);
                    MMA16816(acc[mt][nb * 2 + 1], Ah[mt], Bl[nb] + 2);
                    MMA16816(acc[mt][nb * 2 + 1], Al[mt], Bh[nb] + 2);
                }
        }
        __syncthreads();
    }

    float* op = g_part + (size_t)ksp * VOX;
    #pragma unroll
    for (int mt = 0; mt < 2; mt++) {
        int px = px0 + wm * 32 + mt * 16 + gid;
        #pragma unroll
        for (int n = 0; n < 6; n++) {
            int d0 = wn * 48 + n * 8 + 2 * tig;
            op[(size_t)d0 * PLANE + px]           = acc[mt][n][0];
            op[(size_t)(d0 + 1) * PLANE + px]     = acc[mt][n][1];
            op[(size_t)d0 * PLANE + px + 8]       = acc[mt][n][2];
            op[(size_t)(d0 + 1) * PLANE + px + 8] = acc[mt][n][3];
        }
    }
}

// =============== K2: masked conv3d, kw-split across 12 warps (R11-validated) ===============
__global__ __launch_bounds__(384)
void conv3d_mma_kernel(const float* __restrict__ x, const float* __restrict__ b1) {
    extern __shared__ char cs[];
    const uint32_t sb = smem_u32(cs);
    const int tid = threadIdx.x;
    const int lane = tid & 31, wrp = tid >> 5;
    const int hrow = (wrp < 6) ? wrp : wrp - 6;
    const int khalf = (wrp < 6) ? 0 : 1;
    const int gid = lane >> 2, tig = lane & 3;
    const int amat = lane >> 3, arow = lane & 7;
    const int brow = (lane & 15) & 7, bhf = (lane & 15) >> 3;

    const int d = blockIdx.x >> 3, hb = blockIdx.x & 7;
    const int h0 = hb * 6;

    float* s_xw = (float*)(cs + C_XW);
    for (int i = tid; i < 6 * 16 * 64; i += 384) {
        int s = i >> 10, rem = i & 1023;
        int r = rem >> 6, wxx = rem & 63;
        int sd = d - 5 + s, gh = h0 - 5 + r, gw = wxx - 5;
        float v = 0.f;
        if (sd >= 0 && gh >= 0 && gh < 48 && gw >= 0 && gw < 48)
            v = x[(size_t)sd * PLANE + gh * 48 + gw];
        s_xw[i] = v;
    }
    {
        float4* wdst = (float4*)(cs + C_WH);
        const float4* wsrc = (const float4*)(g_pack + PK_WT);
        for (int i = tid; i < (2 * WT_U32_HALF) / 4; i += 384) wdst[i] = wsrc[i];
    }
    __syncthreads();

    {
        int r = tid;
        int hr = r >> 6, wx = r & 63;
        #pragma unroll
        for (int i = 0; i < 32; i++) {
            const int k0 = 2 * i, k1 = 2 * i + 1;
            float v0 = 0.f, v1 = 0.f;
            if (k0 <= 60) v0 = s_xw[((k0 / 11) * 16 + hr + (k0 % 11)) * 64 + wx];
            if (k1 <= 60) v1 = s_xw[((k1 / 11) * 16 + hr + (k1 % 11)) * 64 + wx];
            uint32_t hv, lv;
            fsplit2(v0, v1, hv, lv);
            *(uint32_t*)(cs + C_AH + r * 144 + i * 4) = hv;
            *(uint32_t*)(cs + C_AL + r * 144 + i * 4) = lv;
        }
    }
    __syncthreads();

    float acc[3][3][4];
    #pragma unroll
    for (int mt = 0; mt < 3; mt++)
        #pragma unroll
        for (int n = 0; n < 3; n++)
            #pragma unroll
            for (int c = 0; c < 4; c++) acc[mt][n][c] = 0.f;

    const int kw_lo = khalf * 6, kw_hi = khalf ? 11 : 6;
    #pragma unroll 1
    for (int kw = kw_lo; kw < kw_hi; kw++) {
        #pragma unroll
        for (int k16 = 0; k16 < 4; k16++) {
            uint32_t bh[3][2], bl[3][2];
            #pragma unroll
            for (int n = 0; n < 3; n++) {
                uint32_t boff = (uint32_t)((kw * 24 + n * 8 + brow) * 144 + k16 * 32 + bhf * 16);
                LDSM2(bh[n], sb + C_WH + boff);
                LDSM2(bl[n], sb + C_WL + boff);
            }
            #pragma unroll
            for (int mt = 0; mt < 3; mt++) {
                int rowbase = hrow * 64 + mt * 16 + kw;
                uint32_t aoff = (uint32_t)((rowbase + arow + (amat & 1) * 8) * 144
                                           + k16 * 32 + (amat >> 1) * 16);
                uint32_t Ah[4], Al[4];
                LDSM4(Ah, sb + C_AH + aoff);
                LDSM4(Al, sb + C_AL + aoff);
                #pragma unroll
                for (int n = 0; n < 3; n++) {
                    MMA16816(acc[mt][n], Ah, bh[n]);
                    MMA16816(acc[mt][n], Ah, bl[n]);
                    MMA16816(acc[mt][n], Al, bh[n]);
                }
            }
        }
    }

    __syncthreads();
    float* exch = (float*)(cs + C_AL);
    if (khalf == 1) {
        float* e = exch + ((wrp - 6) * 32 + lane) * 37;
        #pragma unroll
        for (int mt = 0; mt < 3; mt++)
            #pragma unroll
            for (int n = 0; n < 3; n++)
                #pragma unroll
                for (int c = 0; c < 4; c++)
                    e[(mt * 3 + n) * 4 + c] = acc[mt][n][c];
    }
    __syncthreads();
    if (khalf == 0) {
        const float* e = exch + (wrp * 32 + lane) * 37;
        float bb1[3][2];
        #pragma unroll
        for (int n = 0; n < 3; n++) {
            int c0 = n * 8 + 2 * tig;
            bb1[n][0] = b1[c0]; bb1[n][1] = b1[c0 + 1];
        }
        const int h_glob = h0 + hrow;
        #pragma unroll
        for (int mt = 0; mt < 3; mt++) {
            int px0 = mt * 16 + gid, px1 = px0 + 8;
            #pragma unroll
            for (int n = 0; n < 3; n++) {
                int c0 = n * 8 + 2 * tig;
                const float* ep = e + (mt * 3 + n) * 4;
                float* o0 = g_x1 + ((size_t)d * 24 + c0) * PLANE + h_glob * 48;
                float* o1 = g_x1 + ((size_t)d * 24 + c0 + 1) * PLANE + h_glob * 48;
                o0[px0] = acc[mt][n][0] + ep[0] + bb1[n][0];
                o1[px0] = acc[mt][n][1] + ep[1] + bb1[n][1];
                o0[px1] = acc[mt][n][2] + ep[2] + bb1[n][0];
                o1[px1] = acc[mt][n][3] + ep[3] + bb1[n][1];
            }
        }
    }
}

// =============== K3: MLP, 256 voxels/CTA, fast splits (R14-validated) ===============
__global__ __launch_bounds__(256)
void mlp_mma_kernel(const float* __restrict__ x, const float* __restrict__ b3,
                    float* __restrict__ out)
{
    extern __shared__ char sm_[];
    const uint32_t sb = smem_u32(sm_);
    const int tid = threadIdx.x;
    const int lane = tid & 31, w = tid >> 5;
    const int gid = lane >> 2, tig = lane & 3;

    for (int i = tid; i < PW_BYTES / 16; i += 256)
        ((uint4*)sm_)[i] = ((const uint4*)g_mlpw)[i];

    float* s_ba = (float*)(sm_ + PW_BA);
    float* s_bb = (float*)(sm_ + PW_BB);
    float* s_bc = (float*)(sm_ + PW_BC);
    float* s_ex = (float*)(sm_ + MO_EX);

    const int v = blockIdx.x * 256 + tid;
    const int dd = v / PLANE, p = v % PLANE;
    {
        const float* xb = g_x1 + (size_t)dd * 24 * PLANE + p;
        float t[26];
        #pragma unroll
        for (int c = 0; c < 24; c++) t[c] = xb[(size_t)c * PLANE];
        t[24] = g_part[v] + g_part[VOX + v] + g_part[2 * (size_t)VOX + v]
              + g_part[3 * (size_t)VOX + v] + b3[dd];
        t[25] = 0.f;
        #pragma unroll
        for (int i = 0; i < 13; i++) {
            uint32_t hv, lv;
            fsplit2(t[2 * i], t[2 * i + 1], hv, lv);
            *(uint32_t*)(sm_ + MO_XH + tid * XP + 4 * i) = hv;
            *(uint32_t*)(sm_ + MO_XL + tid * XP + 4 * i) = lv;
        }
        #pragma unroll
        for (int i = 13; i < 16; i++) {
            *(uint32_t*)(sm_ + MO_XH + tid * XP + 4 * i) = 0;
            *(uint32_t*)(sm_ + MO_XL + tid * XP + 4 * i) = 0;
        }
    }
    __syncthreads();

    const int amat = lane >> 3, arow = lane & 7;
    const int bl15 = lane & 15, brow = bl15 & 7, bhf = bl15 >> 3;
    #define AADDR(off, row0, kb, P) \
        (sb + (off) + (uint32_t)(((row0) + arow + (amat & 1) * 8) * (P) + (kb) + (amat >> 1) * 16))
    #define BADDR(off, n0, kb, P) \
        (sb + (off) + (uint32_t)(((n0) + brow) * (P) + (kb) + bhf * 16))

    const int row0 = w * 32;

    float dA[2][6][4];
    #pragma unroll
    for (int m = 0; m < 2; m++)
        #pragma unroll
        for (int n = 0; n < 6; n++)
            #pragma unroll
            for (int c = 0; c < 4; c++) dA[m][n][c] = 0.f;
    {
        uint32_t Ahf[2][2][4], Alf[2][2][4];
        #pragma unroll
        for (int m = 0; m < 2; m++)
            #pragma unroll
            for (int k = 0; k < 2; k++) {
                LDSM4(Ahf[m][k], AADDR(MO_XH, row0 + 16 * m, 32 * k, XP));
                LDSM4(Alf[m][k], AADDR(MO_XL, row0 + 16 * m, 32 * k, XP));
            }
        #pragma unroll
        for (int n = 0; n < 6; n++) {
            uint32_t bh[2][2], bl2[2][2];
            #pragma unroll
            for (int k = 0; k < 2; k++) {
                LDSM2(bh[k],  BADDR(PW_AH, n * 8, 32 * k, WP));
                LDSM2(bl2[k], BADDR(PW_AL, n * 8, 32 * k, WP));
            }
            #pragma unroll
            for (int m = 0; m < 2; m++)
                #pragma unroll
                for (int k = 0; k < 2; k++) {
                    MMA16816(dA[m][n], Ahf[m][k], bh[k]);
                    MMA16816(dA[m][n], Ahf[m][k], bl2[k]);
                    MMA16816(dA[m][n], Alf[m][k], bh[k]);
                }
        }
    }
    #pragma unroll
    for (int m = 0; m < 2; m++)
        #pragma unroll
        for (int n = 0; n < 6; n++) {
            float2 bias = *(float2*)(s_ba + n * 8 + 2 * tig);
            float v0 = fmaxf(dA[m][n][0] + bias.x, 0.f);
            float v1 = fmaxf(dA[m][n][1] + bias.y, 0.f);
            float v2 = fmaxf(dA[m][n][2] + bias.x, 0.f);
            float v3 = fmaxf(dA[m][n][3] + bias.y, 0.f);
            int r1 = row0 + 16 * m + gid, r2 = r1 + 8;
            int cb = (n * 8 + 2 * tig) * 2;
            uint32_t hv, lv;
            fsplit2(v0, v1, hv, lv);
            *(uint32_t*)(sm_ + MO_XH + r1 * XP + cb) = hv;
            *(uint32_t*)(sm_ + MO_XL + r1 * XP + cb) = lv;
            fsplit2(v2, v3, hv, lv);
            *(uint32_t*)(sm_ + MO_XH + r2 * XP + cb) = hv;
            *(uint32_t*)(sm_ + MO_XL + r2 * XP + cb) = lv;
        }
    __syncwarp();

    float dB[2][12][4];
    #pragma unroll
    for (int m = 0; m < 2; m++)
        #pragma unroll
        for (int n = 0; n < 12; n++)
            #pragma unroll
            for (int c = 0; c < 4; c++) dB[m][n][c] = 0.f;
    {
        uint32_t Ahf[2][3][4], Alf[2][3][4];
        #pragma unroll
        for (int m = 0; m < 2; m++)
            #pragma unroll
            for (int k = 0; k < 3; k++) {
                LDSM4(Ahf[m][k], AADDR(MO_XH, row0 + 16 * m, 32 * k, XP));
                LDSM4(Alf[m][k], AADDR(MO_XL, row0 + 16 * m, 32 * k, XP));
            }
        #pragma unroll
        for (int n = 0; n < 12; n++) {
            uint32_t bh[3][2], bl2[3][2];
            #pragma unroll
            for (int k = 0; k < 3; k++) {
                LDSM2(bh[k],  BADDR(PW_BH, n * 8, 32 * k, WP));
                LDSM2(bl2[k], BADDR(PW_BL, n * 8, 32 * k, WP));
            }
            #pragma unroll
            for (int m = 0; m < 2; m++)
                #pragma unroll
                for (int k = 0; k < 3; k++) {
                    MMA16816(dB[m][n], Ahf[m][k], bh[k]);
                    MMA16816(dB[m][n], Ahf[m][k], bl2[k]);
                    MMA16816(dB[m][n], Alf[m][k], bh[k]);
                }
        }
    }
    #pragma unroll
    for (int m = 0; m < 2; m++)
        #pragma unroll
        for (int n = 0; n < 12; n++) {
            float2 bias = *(float2*)(s_bb + n * 8 + 2 * tig);
            float v0 = fmaxf(dB[m][n][0] + bias.x, 0.f);
            float v1 = fmaxf(dB[m][n][1] + bias.y, 0.f);
            float v2 = fmaxf(dB[m][n][2] + bias.x, 0.f);
            float v3 = fmaxf(dB[m][n][3] + bias.y, 0.f);
            int r1 = row0 + 16 * m + gid, r2 = r1 + 8;
            int cb = (n * 8 + 2 * tig) * 2;
            uint32_t hv, lv;
            fsplit2(v0, v1, hv, lv);
            *(uint32_t*)(sm_ + MO_XH + r1 * XP + cb) = hv;
            *(uint32_t*)(sm_ + MO_XL + r1 * XP + cb) = lv;
            fsplit2(v2, v3, hv, lv);
            *(uint32_t*)(sm_ + MO_XH + r2 * XP + cb) = hv;
            *(uint32_t*)(sm_ + MO_XL + r2 * XP + cb) = lv;
        }
    __syncwarp();

    float dC[2][2][4];
    #pragma unroll
    for (int m = 0; m < 2; m++)
        #pragma unroll
        for (int n = 0; n < 2; n++)
            #pragma unroll
            for (int c = 0; c < 4; c++) dC[m][n][c] = 0.f;
    {
        uint32_t Ahf[2][6][4], Alf[2][6][4];
        #pragma unroll
        for (int m = 0; m < 2; m++)
            #pragma unroll
            for (int k = 0; k < 6; k++) {
                LDSM4(Ahf[m][k], AADDR(MO_XH, row0 + 16 * m, 32 * k, XP));
                LDSM4(Alf[m][k], AADDR(MO_XL, row0 + 16 * m, 32 * k, XP));
            }
        #pragma unroll
        for (int n = 0; n < 2; n++) {
            #pragma unroll
            for (int k = 0; k < 6; k++) {
                uint32_t bh[2], bl2[2];
                LDSM2(bh,  BADDR(PW_CH, n * 8, 32 * k, CP));
                LDSM2(bl2, BADDR(PW_CL, n * 8, 32 * k, CP));
                #pragma unroll
                for (int m = 0; m < 2; m++) {
                    MMA16816(dC[m][n], Ahf[m][k], bh);
                    MMA16816(dC[m][n], Ahf[m][k], bl2);
                    MMA16816(dC[m][n], Alf[m][k], bh);
                }
            }
        }
    }

    #pragma unroll
    for (int m = 0; m < 2; m++)
        #pragma unroll
        for (int n = 0; n < 2; n++) {
            int r1 = row0 + 16 * m + gid, r2 = r1 + 8;
            int cc = n * 8 + 2 * tig;
            s_ex[r1 * 18 + cc]     = dC[m][n][0];
            s_ex[r1 * 18 + cc + 1] = dC[m][n][1];
            s_ex[r2 * 18 + cc]     = dC[m][n][2];
            s_ex[r2 * 18 + cc + 1] = dC[m][n][3];
        }
    __syncwarp();

    float o9[9];
    #pragma unroll
    for (int o = 0; o < 9; o++) o9[o] = s_ex[tid * 18 + o] + s_bc[o];

    float xv = x[v];
    float mx = fmaxf(o9[6], fmaxf(o9[7], o9[8]));
    float e0 = expf(o9[6] - mx), e1 = expf(o9[7] - mx), e2 = expf(o9[8] - mx);
    float inv = 1.f / (e0 + e1 + e2);
    float wsm[3] = {e0 * inv, e1 * inv, e2 * inv};

    float p3 = 0.f;
    #pragma unroll
    for (int k = 0; k < 3; k++) {
        float mu = o9[k];
        float scv = o9[3 + k];
        if (scv == 0.f) scv = 1e-9f;
        scv = fabsf(scv);
        float invs = 1.f / scv;
        float l = fabsf(normcdff((xv + 0.5f - mu) * invs)
                      - normcdff((xv - 0.5f - mu) * invs));
        p3 = fmaf(wsm[k], l, p3);
    }

    out[v] = p3;
    #pragma unroll
    for (int o = 0; o < 9; o++)
        out[(size_t)VOX + (size_t)o * VOX + v] = o9[o];
    #undef AADDR
    #undef BADDR
}

extern "C" void kernel_launch(void* const* d_in, const int* in_sizes, int n_in,
                              void* d_out, int out_size) {
    const float* x     = (const float*)d_in[0];
    const float* hyper = (const float*)d_in[1];
    const float* W3    = (const float*)d_in[2];
    const float* b3    = (const float*)d_in[3];
    const float* W1    = (const float*)d_in[4];
    const float* b1    = (const float*)d_in[5];
    const float* Wa    = (const float*)d_in[6];
    const float* ba    = (const float*)d_in[7];
    const float* Wb    = (const float*)d_in[8];
    const float* bb    = (const float*)d_in[9];
    const float* Wc    = (const float*)d_in[10];
    const float* bc    = (const float*)d_in[11];
    float* out = (float*)d_out;

    cudaFuncSetAttribute(conv3d_mma_kernel,
                         cudaFuncAttributeMaxDynamicSharedMemorySize, C_SMEM);
    cudaFuncSetAttribute(conv2d_mma_kernel,
                         cudaFuncAttributeMaxDynamicSharedMemorySize, G_SMEM);
    cudaFuncSetAttribute(mlp_mma_kernel,
                         cudaFuncAttributeMaxDynamicSharedMemorySize, MO_SMEM);

    pack_kernel<<<256, 256>>>(W3, W1, Wa, ba, Wb, bb, Wc, bc);
    im2col_kernel<<<dim3((KK + 255) / 256, PLANE / 4), 256>>>(hyper);
    conv2d_mma_kernel<<<36 * KSPLIT, 256, G_SMEM>>>();
    conv3d_mma_kernel<<<192 * 8, 384, C_SMEM>>>(x, b1);
    mlp_mma_kernel<<<VOX / 256, 256, MO_SMEM>>>(x, b3, out);
}